// round 10
// baseline (speedup 1.0000x reference)
#include <cuda_runtime.h>

#define N_PTS 8192
#define GRIDW 96
#define NBUCK 128
#define CAP   52
#define CELL_CAP 24
#define KSCALE 44739242.0f   // ~2^32/96 ; 96*KSCALE = 4294967232 < 2^32

// smem words: lists 256*CAP | len 256 | HB 256*65 | HBsT 96*256 u16 | part 256*4
#define SMW_LISTS (256*CAP)
#define SMW_LEN   256
#define SMW_HB    (256*65)
#define SMW_HBST  (GRIDW*256/2)
#define SMW_PART  (256*4)
#define SMEM_SEL  ((SMW_LISTS + SMW_LEN + SMW_HB + SMW_HBST + SMW_PART) * 4)

// ---------------- scratch (device globals; no allocation) ----------------
__device__ int    d_cellcnt[4096];              // zero-init; re-zeroed by select blk 0
__device__ float4 d_cellpts[4096 * CELL_CAP];   // (x, y, z, bitcast point idx)
__device__ float  d_nn[N_PTS];                  // exact nn distance

__device__ __forceinline__ int cell_coord(float v) {
    int c = (int)floorf((v + 48.0f) * (1.0f / 6.0f));
    return min(max(c, 0), 15);
}

// ---------------- kernel 0: scatter points into cells ----------------
__global__ void build_cells(const float* __restrict__ pts) {
    int i = blockIdx.x * 256 + threadIdx.x;
    float x = pts[3*i+0] * 96.0f;
    float y = pts[3*i+1] * 96.0f;
    float z = pts[3*i+2] * 96.0f;
    int c = (cell_coord(z) * 16 + cell_coord(y)) * 16 + cell_coord(x);
    int pos = atomicAdd(&d_cellcnt[c], 1);
    if (pos < CELL_CAP)
        d_cellpts[c * CELL_CAP + pos] = make_float4(x, y, z, __int_as_float(i));
}

// ---------------- kernel 1: exact NN via expanding Chebyshev shells ----------------
__global__ void nn_kernel(const float* __restrict__ pts) {
    int i = blockIdx.x * 256 + threadIdx.x;
    float mx = pts[3*i+0] * 96.0f;
    float my = pts[3*i+1] * 96.0f;
    float mz = pts[3*i+2] * 96.0f;
    int cx = cell_coord(mx), cy = cell_coord(my), cz = cell_coord(mz);

    float mind2 = __int_as_float(0x7f800000);
    for (int R = 1; R <= 15; R++) {
        int zlo = max(cz - R, 0), zhi = min(cz + R, 15);
        int ylo = max(cy - R, 0), yhi = min(cy + R, 15);
        int xlo = max(cx - R, 0), xhi = min(cx + R, 15);
        for (int iz = zlo; iz <= zhi; iz++)
        for (int iy = ylo; iy <= yhi; iy++)
        for (int ix = xlo; ix <= xhi; ix++) {
            if (R > 1 && abs(iz - cz) < R && abs(iy - cy) < R && abs(ix - cx) < R)
                continue;   // interior already scanned
            int c = (iz * 16 + iy) * 16 + ix;
            int cnt = min(d_cellcnt[c], CELL_CAP);
            int base = c * CELL_CAP;
            for (int k = 0; k < cnt; k++) {
                float4 q = d_cellpts[base + k];
                if (__float_as_int(q.w) == i) continue;
                float dx = q.x - mx, dy = q.y - my, dzv = q.z - mz;
                float d2 = fmaf(dx, dx, fmaf(dy, dy, dzv * dzv));
                mind2 = fminf(mind2, d2);
            }
        }
        float rr = 6.0f * (float)R - 0.01f;   // fp-safety margin on the guarantee
        if (mind2 <= rr * rr) break;
    }
    d_nn[i] = sqrtf(fmaxf(mind2, 0.0f));
}

// exact bucket: max j in [0,127] with px >= thr(j), thr(j) = (float)(j-48) - dd
__device__ __forceinline__ int bucket_of(float px, float dd) {
    int b = (int)floorf(px + 48.0f + dd);
    if (b < 0) b = 0;
    if (b > NBUCK-1) b = NBUCK-1;
    while (b < NBUCK-1 && px >= ((float)(b + 1 - 48) - dd)) b++;
    while (b > 0       && px <  ((float)(b     - 48) - dd)) b--;
    return b;
}

// locate bin for global rank r from per-lane 8 u16 counts (w4), warp-inclusive cum
__device__ __forceinline__ void find_bin(uint4 w4, unsigned cum, unsigned s8,
                                         unsigned r, int lane,
                                         int& bin, unsigned& rloc) {
    unsigned bal = __ballot_sync(0xffffffffu, r < cum);
    int L = __ffs(bal) - 1;
    unsigned base = __shfl_sync(0xffffffffu, cum - s8, L);
    unsigned vx = __shfl_sync(0xffffffffu, w4.x, L);
    unsigned vy = __shfl_sync(0xffffffffu, w4.y, L);
    unsigned vz = __shfl_sync(0xffffffffu, w4.z, L);
    unsigned vw = __shfl_sync(0xffffffffu, w4.w, L);
    unsigned cnt[8] = { vx & 0xffffu, vx >> 16, vy & 0xffffu, vy >> 16,
                        vz & 0xffffu, vz >> 16, vw & 0xffffu, vw >> 16 };
    unsigned rr = r - base;
    unsigned pre = 0; int k = 0;
    #pragma unroll
    for (int q = 0; q < 8; q++) { pre += cnt[q]; if (rr >= pre) k++; }
    unsigned pfx = 0;
    #pragma unroll
    for (int q = 0; q < 8; q++) if (q < k) pfx += cnt[q];
    bin = L * 8 + k;
    rloc = rr - pfx;
}

// warp-cooperative: values at active-ranks r0 and r1 within one bin list
__device__ __forceinline__ void bin_select2(const unsigned* __restrict__ bl, int L,
                                            int j, unsigned r0, unsigned r1, int lane,
                                            unsigned& k0, unsigned& k1) {
    unsigned v0 = 0, v1 = 0; int a0 = 0, a1 = 0;
    if (lane < L)      { v0 = bl[lane];      a0 = (int)(v0 & 127u) >= j; }
    if (lane + 32 < L) { v1 = bl[lane + 32]; a1 = (int)(v1 & 127u) >= j; }
    unsigned c0 = 0, c1 = 0;
    for (int q = 0; q < L; q++) {
        unsigned u = bl[q];                       // broadcast read
        if ((int)(u & 127u) >= j) {
            c0 += (unsigned)((u < v0) || (u == v0 && q < lane));
            c1 += (unsigned)((u < v1) || (u == v1 && q < lane + 32));
        }
    }
    unsigned b0 = __ballot_sync(0xffffffffu, a0 && c0 == r0);
    unsigned b1 = __ballot_sync(0xffffffffu, a1 && c1 == r0);
    k0 = b0 ? __shfl_sync(0xffffffffu, v0, __ffs(b0) - 1)
            : __shfl_sync(0xffffffffu, v1, __ffs(b1) - 1);
    unsigned d0 = __ballot_sync(0xffffffffu, a0 && c0 == r1);
    unsigned d1 = __ballot_sync(0xffffffffu, a1 && c1 == r1);
    k1 = d0 ? __shfl_sync(0xffffffffu, v0, __ffs(d0) - 1)
            : __shfl_sync(0xffffffffu, v1, __ffs(d1) - 1);
}

// ---------------- kernel 2: one block per ROW, 1024 threads ----------------
__global__ void __launch_bounds__(1024, 1) select_kernel(const float* __restrict__ pts,
                                                         float* __restrict__ out) {
    extern __shared__ unsigned sm[];
    unsigned* lists = sm;                          // [256][CAP]
    unsigned* len   = sm + SMW_LISTS;              // [256]
    unsigned* HB    = len + SMW_LEN;               // [256][65] u16-pair histogram
    unsigned short* HBsT = (unsigned short*)(HB + SMW_HB);   // [96][256] u16
    unsigned* part  = HB + SMW_HB + SMW_HBST;      // [256][4] after HBsT
    __shared__ float s_red[32];
    __shared__ float s_dd;

    const int row  = blockIdx.x;
    const int tid  = threadIdx.x;
    const int lane = tid & 31, wid = tid >> 5;

    // re-zero cell counters for the next launch (block 0 only)
    if (row == 0)
        for (int w = tid; w < 4096; w += 1024) d_cellcnt[w] = 0;

    // --- fused delta2 reduction (deterministic, redundant per block) ---
    float acc = 0.0f;
    for (int i = tid; i < N_PTS; i += 1024)
        acc += d_nn[i];
    #pragma unroll
    for (int o = 16; o > 0; o >>= 1) acc += __shfl_down_sync(0xffffffffu, acc, o);
    if (lane == 0) s_red[wid] = acc;
    // zero len + HB concurrently
    for (int w = tid; w < SMW_LEN + SMW_HB; w += 1024) len[w] = 0;
    __syncthreads();
    if (tid < 32) {
        float v = s_red[tid];
        #pragma unroll
        for (int o = 16; o > 0; o >>= 1) v += __shfl_down_sync(0xffffffffu, v, o);
        if (tid == 0) s_dd = 3.0f * (3.0f * (v * (1.0f / 8192.0f)));
    }
    __syncthreads();
    const float dd  = s_dd;
    const float Yr  = (float)(row - 48);
    const float ylo = Yr - dd, yhi = Yr + dd;

    // --- phase 1: bin lists + (bin,bucket) histogram (inline prep) ---
    for (int i = tid; i < N_PTS; i += 1024) {
        float px = pts[3*i+0] * 96.0f;
        float py = pts[3*i+1] * 96.0f;
        if (px <= yhi && py >= ylo && py <= yhi) {
            float pz = pts[3*i+2] * 96.0f;
            int b = bucket_of(px, dd);
            unsigned key = __float2uint_rz((pz + 48.0f) * KSCALE);
            unsigned bin = key >> 24;
            unsigned packed = (key & 0xFFFFFF80u) | (unsigned)b;
            unsigned pos = atomicAdd(&len[bin], 1u);
            if (pos < CAP) lists[bin * CAP + pos] = packed;
            atomicAdd(&HB[bin * 65 + (b >> 1)], 1u << (16 * (b & 1)));
        }
    }
    __syncthreads();

    // --- phase 2a: per-(bin, quarter) partial sums ---
    {
        int b = tid & 255, q = tid >> 8;
        unsigned s = 0;
        for (int w = 16*q; w < 16*q + 16; w++) {
            unsigned word = HB[b * 65 + w];
            s += (word & 0xffffu) + (word >> 16);
        }
        part[b * 4 + q] = s;
    }
    __syncthreads();
    // --- phase 2b: suffix counts, transposed ---
    {
        int b = tid & 255, q = tid >> 8;
        unsigned s = 0;
        for (int qq = q + 1; qq < 4; qq++) s += part[b * 4 + qq];
        for (int w = 16*q + 15; w >= 16*q; w--) {
            unsigned word = HB[b * 65 + w];
            unsigned hi = word >> 16, lo = word & 0xffffu;
            int bk = 2 * w + 1;
            s += hi;
            if (bk < GRIDW)     HBsT[bk * 256 + b]       = (unsigned short)s;
            s += lo;
            if (bk - 1 < GRIDW) HBsT[(bk - 1) * 256 + b] = (unsigned short)s;
        }
    }
    __syncthreads();

    // --- phase 3: 32 warps x 3 columns ---
    for (int j = wid; j < GRIDW; j += 32) {
        uint4 w4 = ((const uint4*)(HBsT + j * 256))[lane];    // 8 bins per lane
        unsigned s8 = (w4.x & 0xffffu) + (w4.x >> 16) + (w4.y & 0xffffu) + (w4.y >> 16)
                    + (w4.z & 0xffffu) + (w4.z >> 16) + (w4.w & 0xffffu) + (w4.w >> 16);
        unsigned cum = s8;
        #pragma unroll
        for (int o = 1; o < 32; o <<= 1) {
            unsigned u = __shfl_up_sync(0xffffffffu, cum, o);
            if (lane >= o) cum += u;
        }
        unsigned c = __shfl_sync(0xffffffffu, cum, 31);
        if (c == 0) { if (lane == 0) out[row * GRIDW + j] = 0.0f; continue; }

        unsigned rlo = (c - 1) >> 1, rhi = c >> 1;
        int binlo, binhi; unsigned rl2, rh2;
        find_bin(w4, cum, s8, rlo, lane, binlo, rl2);
        find_bin(w4, cum, s8, rhi, lane, binhi, rh2);

        unsigned klo, khi;
        if (binlo == binhi) {
            int L = (int)min(len[binlo], (unsigned)CAP);
            bin_select2(lists + binlo * CAP, L, j, rl2, rh2, lane, klo, khi);
        } else {
            unsigned t0;
            int L0 = (int)min(len[binlo], (unsigned)CAP);
            bin_select2(lists + binlo * CAP, L0, j, rl2, rl2, lane, klo, t0);
            int L1 = (int)min(len[binhi], (unsigned)CAP);
            bin_select2(lists + binhi * CAP, L1, j, rh2, rh2, lane, khi, t0);
        }

        if (lane == 0) {
            float vlo = ((float)(klo & 0xFFFFFF80u) + 64.0f) * (1.0f / KSCALE) - 48.0f;
            float vhi = ((float)(khi & 0xFFFFFF80u) + 64.0f) * (1.0f / KSCALE) - 48.0f;
            out[row * GRIDW + j] = (0.5f * (vlo + vhi) + 48.0f) * (1.0f / 96.0f);
        }
    }
}

// ---------------- launch ----------------
extern "C" void kernel_launch(void* const* d_in, const int* in_sizes, int n_in,
                              void* d_out, int out_size) {
    const float* pts = (const float*)d_in[0];
    float* out = (float*)d_out;

    cudaFuncSetAttribute(select_kernel, cudaFuncAttributeMaxDynamicSharedMemorySize, SMEM_SEL);

    build_cells<<<32, 256>>>(pts);
    nn_kernel<<<32, 256>>>(pts);
    select_kernel<<<GRIDW, 1024, SMEM_SEL>>>(pts, out);
}

// round 14
// speedup vs baseline: 1.8857x; 1.8857x over previous
#include <cuda_runtime.h>

#define N_PTS 8192
#define GRIDW 96
#define NBUCK 128
#define CAP   52
#define CELL_CAP 24
#define KSCALE 44739242.0f   // ~2^32/96 ; 96*KSCALE = 4294967232 < 2^32
#define YBINS 256
#define YSCALE 2.66666666667f   // 256/96

// smem words: lists 256*CAP | len 256 | HB 256*65 | HBsT 96*256 u16 | part 256*4
#define SMW_LISTS (256*CAP)
#define SMW_LEN   256
#define SMW_HB    (256*65)
#define SMW_HBST  (GRIDW*256/2)
#define SMW_PART  (256*4)
#define SMEM_SEL  ((SMW_LISTS + SMW_LEN + SMW_HB + SMW_HBST + SMW_PART) * 4)

// ---------------- scratch (device globals; no allocation) ----------------
__device__ int    d_cellcnt[4096];              // zero-init; re-zeroed by select blk 0
__device__ float4 d_cellpts[4096 * CELL_CAP];   // (x, y, z, bitcast point idx)
__device__ float  d_nn[N_PTS];
__device__ float  d_dd;
__device__ int    d_yoff[YBINS + 1];
__device__ float4 d_sorted[N_PTS];              // (py, px, bitcast packed, 0)

__device__ __forceinline__ int cell_coord(float v) {
    int c = (int)floorf((v + 48.0f) * (1.0f / 6.0f));
    return min(max(c, 0), 15);
}
__device__ __forceinline__ int ybin_of(float py) {
    int b = (int)floorf((py + 48.0f) * YSCALE);
    return min(max(b, 0), YBINS - 1);
}

// ---------------- kernel 0: scatter points into cells ----------------
__global__ void build_cells(const float* __restrict__ pts) {
    int i = blockIdx.x * 256 + threadIdx.x;
    float x = pts[3*i+0] * 96.0f;
    float y = pts[3*i+1] * 96.0f;
    float z = pts[3*i+2] * 96.0f;
    int c = (cell_coord(z) * 16 + cell_coord(y)) * 16 + cell_coord(x);
    int pos = atomicAdd(&d_cellcnt[c], 1);
    if (pos < CELL_CAP)
        d_cellpts[c * CELL_CAP + pos] = make_float4(x, y, z, __int_as_float(i));
}

// ---------------- kernel 1: exact NN, ONE WARP PER POINT ----------------
__global__ void __launch_bounds__(1024) nn_kernel(const float* __restrict__ pts) {
    const int lane = threadIdx.x & 31;
    const int i = (blockIdx.x * blockDim.x + threadIdx.x) >> 5;   // warp id = point

    float mx = pts[3*i+0] * 96.0f;
    float my = pts[3*i+1] * 96.0f;
    float mz = pts[3*i+2] * 96.0f;
    int cx = cell_coord(mx), cy = cell_coord(my), cz = cell_coord(mz);

    float mind2 = __int_as_float(0x7f800000);
    for (int R = 1; R <= 16; R++) {
        int side = 2*R + 1, side2 = side * side, ncell = side2 * side;
        for (int t = lane; t < ncell; t += 32) {
            int tz = t / side2, rem = t - tz * side2;
            int ty = rem / side, tx = rem - ty * side;
            int iz = cz - R + tz, iy = cy - R + ty, ix = cx - R + tx;
            if ((unsigned)iz > 15u || (unsigned)iy > 15u || (unsigned)ix > 15u) continue;
            if (R > 1 && abs(iz-cz) < R && abs(iy-cy) < R && abs(ix-cx) < R) continue;
            int c = (iz * 16 + iy) * 16 + ix;
            int cnt = min(d_cellcnt[c], CELL_CAP);
            int base = c * CELL_CAP;
            for (int k = 0; k < cnt; k++) {
                float4 q = d_cellpts[base + k];
                if (__float_as_int(q.w) == i) continue;
                float dx = q.x - mx, dy = q.y - my, dzv = q.z - mz;
                float d2 = fmaf(dx, dx, fmaf(dy, dy, dzv * dzv));
                mind2 = fminf(mind2, d2);
            }
        }
        #pragma unroll
        for (int o = 16; o > 0; o >>= 1)
            mind2 = fminf(mind2, __shfl_xor_sync(0xffffffffu, mind2, o));
        float rr = 6.0f * (float)R - 0.01f;
        if (mind2 <= rr * rr) break;
    }
    if (lane == 0) d_nn[i] = sqrtf(fmaxf(mind2, 0.0f));
}

// exact bucket: max j in [0,127] with px >= thr(j), thr(j) = (float)(j-48) - dd
__device__ __forceinline__ int bucket_of(float px, float dd) {
    int b = (int)floorf(px + 48.0f + dd);
    if (b < 0) b = 0;
    if (b > NBUCK-1) b = NBUCK-1;
    while (b < NBUCK-1 && px >= ((float)(b + 1 - 48) - dd)) b++;
    while (b > 0       && px <  ((float)(b     - 48) - dd)) b--;
    return b;
}

// ---------------- kernel 2: delta2 + counting sort by y (ONE block) ----------------
__global__ void __launch_bounds__(1024, 1) prep_kernel(const float* __restrict__ pts) {
    __shared__ float s_red[32];
    __shared__ float s_dd;
    __shared__ int hist[YBINS];
    __shared__ int offs[YBINS];
    __shared__ int cur[YBINS];
    __shared__ int wtot[8];

    const int tid = threadIdx.x;
    const int lane = tid & 31, wid = tid >> 5;

    // delta2 (same reduction tree as before -> same bits)
    float acc = 0.0f;
    for (int i = tid; i < N_PTS; i += 1024)
        acc += d_nn[i];
    #pragma unroll
    for (int o = 16; o > 0; o >>= 1) acc += __shfl_down_sync(0xffffffffu, acc, o);
    if (lane == 0) s_red[wid] = acc;
    if (tid < YBINS) hist[tid] = 0;
    __syncthreads();
    if (tid < 32) {
        float v = s_red[tid];
        #pragma unroll
        for (int o = 16; o > 0; o >>= 1) v += __shfl_down_sync(0xffffffffu, v, o);
        if (tid == 0) {
            s_dd = 3.0f * (3.0f * (v * (1.0f / 8192.0f)));
            d_dd = s_dd;
        }
    }
    __syncthreads();
    const float dd = s_dd;

    // histogram y
    for (int i = tid; i < N_PTS; i += 1024) {
        float py = pts[3*i+1] * 96.0f;
        atomicAdd(&hist[ybin_of(py)], 1);
    }
    __syncthreads();

    // inclusive scan of 256 bins (first 256 threads)
    if (tid < YBINS) {
        int v = hist[tid];
        #pragma unroll
        for (int o = 1; o < 32; o <<= 1) {
            int u = __shfl_up_sync(0xffffffffu, v, o);
            if (lane >= o) v += u;
        }
        offs[tid] = v;
        if (lane == 31) wtot[tid >> 5] = v;
    }
    __syncthreads();
    if (tid < YBINS) {
        int add = 0;
        for (int w = 0; w < (tid >> 5); w++) add += wtot[w];
        int inc = offs[tid] + add;
        cur[tid]  = inc - hist[tid];            // exclusive
        d_yoff[tid + 1] = inc;
        if (tid == 0) d_yoff[0] = 0;
    }
    __syncthreads();

    // scatter: (py, px, packed key|bucket)
    for (int i = tid; i < N_PTS; i += 1024) {
        float px = pts[3*i+0] * 96.0f;
        float py = pts[3*i+1] * 96.0f;
        float pz = pts[3*i+2] * 96.0f;
        int b = bucket_of(px, dd);
        unsigned key = __float2uint_rz((pz + 48.0f) * KSCALE);
        unsigned packed = (key & 0xFFFFFF80u) | (unsigned)b;
        int pos = atomicAdd(&cur[ybin_of(py)], 1);
        d_sorted[pos] = make_float4(py, px, __uint_as_float(packed), 0.0f);
    }
}

// locate bin for global rank r from per-lane 8 u16 counts (w4), warp-inclusive cum
__device__ __forceinline__ void find_bin(uint4 w4, unsigned cum, unsigned s8,
                                         unsigned r, int lane,
                                         int& bin, unsigned& rloc) {
    unsigned bal = __ballot_sync(0xffffffffu, r < cum);
    int L = __ffs(bal) - 1;
    unsigned base = __shfl_sync(0xffffffffu, cum - s8, L);
    unsigned vx = __shfl_sync(0xffffffffu, w4.x, L);
    unsigned vy = __shfl_sync(0xffffffffu, w4.y, L);
    unsigned vz = __shfl_sync(0xffffffffu, w4.z, L);
    unsigned vw = __shfl_sync(0xffffffffu, w4.w, L);
    unsigned cnt[8] = { vx & 0xffffu, vx >> 16, vy & 0xffffu, vy >> 16,
                        vz & 0xffffu, vz >> 16, vw & 0xffffu, vw >> 16 };
    unsigned rr = r - base;
    unsigned pre = 0; int k = 0;
    #pragma unroll
    for (int q = 0; q < 8; q++) { pre += cnt[q]; if (rr >= pre) k++; }
    unsigned pfx = 0;
    #pragma unroll
    for (int q = 0; q < 8; q++) if (q < k) pfx += cnt[q];
    bin = L * 8 + k;
    rloc = rr - pfx;
}

// warp-cooperative: values at active-ranks r0 and r1 within one bin list
__device__ __forceinline__ void bin_select2(const unsigned* __restrict__ bl, int L,
                                            int j, unsigned r0, unsigned r1, int lane,
                                            unsigned& k0, unsigned& k1) {
    unsigned v0 = 0, v1 = 0; int a0 = 0, a1 = 0;
    if (lane < L)      { v0 = bl[lane];      a0 = (int)(v0 & 127u) >= j; }
    if (lane + 32 < L) { v1 = bl[lane + 32]; a1 = (int)(v1 & 127u) >= j; }
    unsigned c0 = 0, c1 = 0;
    for (int q = 0; q < L; q++) {
        unsigned u = bl[q];                       // broadcast read
        if ((int)(u & 127u) >= j) {
            c0 += (unsigned)((u < v0) || (u == v0 && q < lane));
            c1 += (unsigned)((u < v1) || (u == v1 && q < lane + 32));
        }
    }
    unsigned b0 = __ballot_sync(0xffffffffu, a0 && c0 == r0);
    unsigned b1 = __ballot_sync(0xffffffffu, a1 && c1 == r0);
    k0 = b0 ? __shfl_sync(0xffffffffu, v0, __ffs(b0) - 1)
            : __shfl_sync(0xffffffffu, v1, __ffs(b1) - 1);
    unsigned d0 = __ballot_sync(0xffffffffu, a0 && c0 == r1);
    unsigned d1 = __ballot_sync(0xffffffffu, a1 && c1 == r1);
    k1 = d0 ? __shfl_sync(0xffffffffu, v0, __ffs(d0) - 1)
            : __shfl_sync(0xffffffffu, v1, __ffs(d1) - 1);
}

// ---------------- kernel 3: one block per ROW, 1024 threads ----------------
__global__ void __launch_bounds__(1024, 1) select_kernel(float* __restrict__ out) {
    extern __shared__ unsigned sm[];
    unsigned* lists = sm;                          // [256][CAP]
    unsigned* len   = sm + SMW_LISTS;              // [256]
    unsigned* HB    = len + SMW_LEN;               // [256][65] u16-pair histogram
    unsigned short* HBsT = (unsigned short*)(HB + SMW_HB);   // [96][256] u16
    unsigned* part  = HB + SMW_HB + SMW_HBST;      // [256][4] after HBsT

    const int row  = blockIdx.x;
    const int tid  = threadIdx.x;
    const int lane = tid & 31, wid = tid >> 5;

    // re-zero cell counters for the next graph replay (block 0 only)
    if (row == 0)
        for (int w = tid; w < 4096; w += 1024) d_cellcnt[w] = 0;

    const float dd  = d_dd;
    const float Yr  = (float)(row - 48);
    const float ylo = Yr - dd, yhi = Yr + dd;
    const int i0 = d_yoff[ybin_of(ylo)];
    const int i1 = d_yoff[min(ybin_of(yhi) + 1, YBINS)];

    // zero len + HB
    for (int w = tid; w < SMW_LEN + SMW_HB; w += 1024) len[w] = 0;
    __syncthreads();

    // --- phase 1: bin lists + (bin,bucket) histogram over y-sorted range ---
    for (int i = i0 + tid; i < i1; i += 1024) {
        float4 q = d_sorted[i];                   // (py, px, packed, 0)
        if (q.x >= ylo && q.x <= yhi && q.y <= yhi) {
            unsigned packed = __float_as_uint(q.z);
            unsigned bin = packed >> 24;
            int b = (int)(packed & 127u);
            unsigned pos = atomicAdd(&len[bin], 1u);
            if (pos < CAP) lists[bin * CAP + pos] = packed;
            atomicAdd(&HB[bin * 65 + (b >> 1)], 1u << (16 * (b & 1)));
        }
    }
    __syncthreads();

    // --- phase 2a: per-(bin, quarter) partial sums ---
    {
        int b = tid & 255, q = tid >> 8;
        unsigned s = 0;
        for (int w = 16*q; w < 16*q + 16; w++) {
            unsigned word = HB[b * 65 + w];
            s += (word & 0xffffu) + (word >> 16);
        }
        part[b * 4 + q] = s;
    }
    __syncthreads();
    // --- phase 2b: suffix counts, transposed ---
    {
        int b = tid & 255, q = tid >> 8;
        unsigned s = 0;
        for (int qq = q + 1; qq < 4; qq++) s += part[b * 4 + qq];
        for (int w = 16*q + 15; w >= 16*q; w--) {
            unsigned word = HB[b * 65 + w];
            unsigned hi = word >> 16, lo = word & 0xffffu;
            int bk = 2 * w + 1;
            s += hi;
            if (bk < GRIDW)     HBsT[bk * 256 + b]       = (unsigned short)s;
            s += lo;
            if (bk - 1 < GRIDW) HBsT[(bk - 1) * 256 + b] = (unsigned short)s;
        }
    }
    __syncthreads();

    // --- phase 3: 32 warps x 3 columns ---
    for (int j = wid; j < GRIDW; j += 32) {
        uint4 w4 = ((const uint4*)(HBsT + j * 256))[lane];    // 8 bins per lane
        unsigned s8 = (w4.x & 0xffffu) + (w4.x >> 16) + (w4.y & 0xffffu) + (w4.y >> 16)
                    + (w4.z & 0xffffu) + (w4.z >> 16) + (w4.w & 0xffffu) + (w4.w >> 16);
        unsigned cum = s8;
        #pragma unroll
        for (int o = 1; o < 32; o <<= 1) {
            unsigned u = __shfl_up_sync(0xffffffffu, cum, o);
            if (lane >= o) cum += u;
        }
        unsigned c = __shfl_sync(0xffffffffu, cum, 31);
        if (c == 0) { if (lane == 0) out[row * GRIDW + j] = 0.0f; continue; }

        unsigned rlo = (c - 1) >> 1, rhi = c >> 1;
        int binlo, binhi; unsigned rl2, rh2;
        find_bin(w4, cum, s8, rlo, lane, binlo, rl2);
        find_bin(w4, cum, s8, rhi, lane, binhi, rh2);

        unsigned klo, khi;
        if (binlo == binhi) {
            int L = (int)min(len[binlo], (unsigned)CAP);
            bin_select2(lists + binlo * CAP, L, j, rl2, rh2, lane, klo, khi);
        } else {
            unsigned t0;
            int L0 = (int)min(len[binlo], (unsigned)CAP);
            bin_select2(lists + binlo * CAP, L0, j, rl2, rl2, lane, klo, t0);
            int L1 = (int)min(len[binhi], (unsigned)CAP);
            bin_select2(lists + binhi * CAP, L1, j, rh2, rh2, lane, khi, t0);
        }

        if (lane == 0) {
            float vlo = ((float)(klo & 0xFFFFFF80u) + 64.0f) * (1.0f / KSCALE) - 48.0f;
            float vhi = ((float)(khi & 0xFFFFFF80u) + 64.0f) * (1.0f / KSCALE) - 48.0f;
            out[row * GRIDW + j] = (0.5f * (vlo + vhi) + 48.0f) * (1.0f / 96.0f);
        }
    }
}

// ---------------- launch ----------------
extern "C" void kernel_launch(void* const* d_in, const int* in_sizes, int n_in,
                              void* d_out, int out_size) {
    const float* pts = (const float*)d_in[0];
    float* out = (float*)d_out;

    cudaFuncSetAttribute(select_kernel, cudaFuncAttributeMaxDynamicSharedMemorySize, SMEM_SEL);

    build_cells<<<32, 256>>>(pts);
    nn_kernel<<<256, 1024>>>(pts);
    prep_kernel<<<1, 1024>>>(pts);
    select_kernel<<<GRIDW, 1024, SMEM_SEL>>>(out);
}

// round 17
// speedup vs baseline: 2.2951x; 1.2171x over previous
#include <cuda_runtime.h>

#define N_PTS 8192
#define GRIDW 96
#define NBUCK 128
#define CAP   52
#define CELL_CAP 24
#define KSCALE 44739242.0f   // ~2^32/96 ; 96*KSCALE = 4294967232 < 2^32
#define YBINS 256
#define YSCALE 2.66666666667f   // 256/96

// smem words: lists 256*CAP | len 256 | HB 256*65 | HBsT 96*256 u16 | part 256*4
#define SMW_LISTS (256*CAP)
#define SMW_LEN   256
#define SMW_HB    (256*65)
#define SMW_HBST  (GRIDW*256/2)
#define SMW_PART  (256*4)
#define SMEM_SEL  ((SMW_LISTS + SMW_LEN + SMW_HB + SMW_HBST + SMW_PART) * 4)

// ---------------- scratch (device globals; no allocation) ----------------
__device__ int    d_cellcnt[4096];              // zero at start; re-zeroed by select blk 0
__device__ int    d_yhist[YBINS];               // same
__device__ float4 d_cellpts[4096 * CELL_CAP];   // (x, y, z, bitcast point idx)
__device__ float  d_nn[N_PTS];
__device__ int    d_yoff[YBINS + 1];
__device__ float4 d_sorted[N_PTS];              // (py, px, bitcast zkey, unused)

__device__ __forceinline__ int cell_coord(float v) {
    int c = (int)floorf((v + 48.0f) * (1.0f / 6.0f));
    return min(max(c, 0), 15);
}
__device__ __forceinline__ int ybin_of(float py) {
    int b = (int)floorf((py + 48.0f) * YSCALE);
    return min(max(b, 0), YBINS - 1);
}

// ---------------- kernel A: cell scatter + y histogram ----------------
__global__ void build_kernel(const float* __restrict__ pts) {
    int i = blockIdx.x * 128 + threadIdx.x;
    float x = pts[3*i+0] * 96.0f;
    float y = pts[3*i+1] * 96.0f;
    float z = pts[3*i+2] * 96.0f;
    int c = (cell_coord(z) * 16 + cell_coord(y)) * 16 + cell_coord(x);
    int pos = atomicAdd(&d_cellcnt[c], 1);
    if (pos < CELL_CAP)
        d_cellpts[c * CELL_CAP + pos] = make_float4(x, y, z, __int_as_float(i));
    atomicAdd(&d_yhist[ybin_of(y)], 1);
}

// ---------------- kernel B: NN (blocks 0..255) + y-sort scatter (block 256) ----------------
__global__ void __launch_bounds__(1024) nn_kernel(const float* __restrict__ pts) {
    const int tid = threadIdx.x;
    const int lane = tid & 31;

    if (blockIdx.x == 256) {
        // ---- y-sort scatter block (independent of d_nn) ----
        __shared__ int offs[YBINS];
        __shared__ int cur[YBINS];
        __shared__ int wtot[8];
        if (tid < YBINS) {
            int v = d_yhist[tid];
            int h = v;
            #pragma unroll
            for (int o = 1; o < 32; o <<= 1) {
                int u = __shfl_up_sync(0xffffffffu, v, o);
                if (lane >= o) v += u;
            }
            offs[tid] = v;
            if (lane == 31) wtot[tid >> 5] = v;
            (void)h;
        }
        __syncthreads();
        if (tid < YBINS) {
            int add = 0;
            for (int w = 0; w < (tid >> 5); w++) add += wtot[w];
            int inc = offs[tid] + add;
            cur[tid] = inc - d_yhist[tid];       // exclusive
            d_yoff[tid + 1] = inc;
            if (tid == 0) d_yoff[0] = 0;
        }
        __syncthreads();
        for (int i = tid; i < N_PTS; i += 1024) {
            float px = pts[3*i+0] * 96.0f;
            float py = pts[3*i+1] * 96.0f;
            float pz = pts[3*i+2] * 96.0f;
            unsigned key = __float2uint_rz((pz + 48.0f) * KSCALE);
            int pos = atomicAdd(&cur[ybin_of(py)], 1);
            d_sorted[pos] = make_float4(py, px, __uint_as_float(key), 0.0f);
        }
        return;
    }

    // ---- warp-per-point exact NN via expanding Chebyshev shells ----
    const int i = (blockIdx.x * 1024 + tid) >> 5;
    float mx = pts[3*i+0] * 96.0f;
    float my = pts[3*i+1] * 96.0f;
    float mz = pts[3*i+2] * 96.0f;
    int cx = cell_coord(mx), cy = cell_coord(my), cz = cell_coord(mz);

    float mind2 = __int_as_float(0x7f800000);
    for (int R = 1; R <= 16; R++) {
        int side = 2*R + 1, side2 = side * side, ncell = side2 * side;
        for (int t = lane; t < ncell; t += 32) {
            int tz = t / side2, rem = t - tz * side2;
            int ty = rem / side, tx = rem - ty * side;
            int iz = cz - R + tz, iy = cy - R + ty, ix = cx - R + tx;
            if ((unsigned)iz > 15u || (unsigned)iy > 15u || (unsigned)ix > 15u) continue;
            if (R > 1 && abs(iz-cz) < R && abs(iy-cy) < R && abs(ix-cx) < R) continue;
            int c = (iz * 16 + iy) * 16 + ix;
            int cnt = min(d_cellcnt[c], CELL_CAP);
            int base = c * CELL_CAP;
            for (int k = 0; k < cnt; k++) {
                float4 q = d_cellpts[base + k];
                if (__float_as_int(q.w) == i) continue;
                float dx = q.x - mx, dy = q.y - my, dzv = q.z - mz;
                float d2 = fmaf(dx, dx, fmaf(dy, dy, dzv * dzv));
                mind2 = fminf(mind2, d2);
            }
        }
        #pragma unroll
        for (int o = 16; o > 0; o >>= 1)
            mind2 = fminf(mind2, __shfl_xor_sync(0xffffffffu, mind2, o));
        float rr = 6.0f * (float)R - 0.01f;
        if (mind2 <= rr * rr) break;
    }
    if (lane == 0) d_nn[i] = sqrtf(fmaxf(mind2, 0.0f));
}

// exact bucket: max j in [0,127] with px >= thr(j), thr(j) = (float)(j-48) - dd
__device__ __forceinline__ int bucket_of(float px, float dd) {
    int b = (int)floorf(px + 48.0f + dd);
    if (b < 0) b = 0;
    if (b > NBUCK-1) b = NBUCK-1;
    while (b < NBUCK-1 && px >= ((float)(b + 1 - 48) - dd)) b++;
    while (b > 0       && px <  ((float)(b     - 48) - dd)) b--;
    return b;
}

// locate bin for global rank r from per-lane 8 u16 counts (w4), warp-inclusive cum
__device__ __forceinline__ void find_bin(uint4 w4, unsigned cum, unsigned s8,
                                         unsigned r, int lane,
                                         int& bin, unsigned& rloc) {
    unsigned bal = __ballot_sync(0xffffffffu, r < cum);
    int L = __ffs(bal) - 1;
    unsigned base = __shfl_sync(0xffffffffu, cum - s8, L);
    unsigned vx = __shfl_sync(0xffffffffu, w4.x, L);
    unsigned vy = __shfl_sync(0xffffffffu, w4.y, L);
    unsigned vz = __shfl_sync(0xffffffffu, w4.z, L);
    unsigned vw = __shfl_sync(0xffffffffu, w4.w, L);
    unsigned cnt[8] = { vx & 0xffffu, vx >> 16, vy & 0xffffu, vy >> 16,
                        vz & 0xffffu, vz >> 16, vw & 0xffffu, vw >> 16 };
    unsigned rr = r - base;
    unsigned pre = 0; int k = 0;
    #pragma unroll
    for (int q = 0; q < 8; q++) { pre += cnt[q]; if (rr >= pre) k++; }
    unsigned pfx = 0;
    #pragma unroll
    for (int q = 0; q < 8; q++) if (q < k) pfx += cnt[q];
    bin = L * 8 + k;
    rloc = rr - pfx;
}

// warp-cooperative: values at active-ranks r0 and r1 within one bin list
__device__ __forceinline__ void bin_select2(const unsigned* __restrict__ bl, int L,
                                            int j, unsigned r0, unsigned r1, int lane,
                                            unsigned& k0, unsigned& k1) {
    unsigned v0 = 0, v1 = 0; int a0 = 0, a1 = 0;
    if (lane < L)      { v0 = bl[lane];      a0 = (int)(v0 & 127u) >= j; }
    if (lane + 32 < L) { v1 = bl[lane + 32]; a1 = (int)(v1 & 127u) >= j; }
    unsigned c0 = 0, c1 = 0;
    for (int q = 0; q < L; q++) {
        unsigned u = bl[q];                       // broadcast read
        if ((int)(u & 127u) >= j) {
            c0 += (unsigned)((u < v0) || (u == v0 && q < lane));
            c1 += (unsigned)((u < v1) || (u == v1 && q < lane + 32));
        }
    }
    unsigned b0 = __ballot_sync(0xffffffffu, a0 && c0 == r0);
    unsigned b1 = __ballot_sync(0xffffffffu, a1 && c1 == r0);
    k0 = b0 ? __shfl_sync(0xffffffffu, v0, __ffs(b0) - 1)
            : __shfl_sync(0xffffffffu, v1, __ffs(b1) - 1);
    unsigned d0 = __ballot_sync(0xffffffffu, a0 && c0 == r1);
    unsigned d1 = __ballot_sync(0xffffffffu, a1 && c1 == r1);
    k1 = d0 ? __shfl_sync(0xffffffffu, v0, __ffs(d0) - 1)
            : __shfl_sync(0xffffffffu, v1, __ffs(d1) - 1);
}

// ---------------- kernel C: one block per ROW, 1024 threads ----------------
__global__ void __launch_bounds__(1024, 1) select_kernel(float* __restrict__ out) {
    extern __shared__ unsigned sm[];
    unsigned* lists = sm;                          // [256][CAP]
    unsigned* len   = sm + SMW_LISTS;              // [256]
    unsigned* HB    = len + SMW_LEN;               // [256][65] u16-pair histogram
    unsigned short* HBsT = (unsigned short*)(HB + SMW_HB);   // [96][256] u16
    unsigned* part  = HB + SMW_HB + SMW_HBST;      // [256][4] after HBsT
    __shared__ float s_red[32];
    __shared__ float s_dd;

    const int row  = blockIdx.x;
    const int tid  = threadIdx.x;
    const int lane = tid & 31, wid = tid >> 5;

    // re-zero scatter counters for the next graph replay (block 0 only)
    if (row == 0) {
        for (int w = tid; w < 4096; w += 1024) d_cellcnt[w] = 0;
        if (tid < YBINS) d_yhist[tid] = 0;
    }

    // --- fused delta2 reduction (deterministic, redundant per block) ---
    float acc = 0.0f;
    for (int i = tid; i < N_PTS; i += 1024)
        acc += d_nn[i];
    #pragma unroll
    for (int o = 16; o > 0; o >>= 1) acc += __shfl_down_sync(0xffffffffu, acc, o);
    if (lane == 0) s_red[wid] = acc;
    // zero len + HB concurrently
    for (int w = tid; w < SMW_LEN + SMW_HB; w += 1024) len[w] = 0;
    __syncthreads();
    if (tid < 32) {
        float v = s_red[tid];
        #pragma unroll
        for (int o = 16; o > 0; o >>= 1) v += __shfl_down_sync(0xffffffffu, v, o);
        if (tid == 0) s_dd = 3.0f * (3.0f * (v * (1.0f / 8192.0f)));
    }
    __syncthreads();
    const float dd  = s_dd;
    const float Yr  = (float)(row - 48);
    const float ylo = Yr - dd, yhi = Yr + dd;
    const int i0 = d_yoff[ybin_of(ylo)];
    const int i1 = d_yoff[min(ybin_of(yhi) + 1, YBINS)];

    // --- phase 1: bin lists + (bin,bucket) histogram over y-sorted range ---
    for (int i = i0 + tid; i < i1; i += 1024) {
        float4 q = d_sorted[i];                   // (py, px, zkey, 0)
        if (q.x >= ylo && q.x <= yhi && q.y <= yhi) {
            int b = bucket_of(q.y, dd);
            unsigned key = __float_as_uint(q.z);
            unsigned bin = key >> 24;
            unsigned packed = (key & 0xFFFFFF80u) | (unsigned)b;
            unsigned pos = atomicAdd(&len[bin], 1u);
            if (pos < CAP) lists[bin * CAP + pos] = packed;
            atomicAdd(&HB[bin * 65 + (b >> 1)], 1u << (16 * (b & 1)));
        }
    }
    __syncthreads();

    // --- phase 2a: per-(bin, quarter) partial sums ---
    {
        int b = tid & 255, q = tid >> 8;
        unsigned s = 0;
        for (int w = 16*q; w < 16*q + 16; w++) {
            unsigned word = HB[b * 65 + w];
            s += (word & 0xffffu) + (word >> 16);
        }
        part[b * 4 + q] = s;
    }
    __syncthreads();
    // --- phase 2b: suffix counts, transposed ---
    {
        int b = tid & 255, q = tid >> 8;
        unsigned s = 0;
        for (int qq = q + 1; qq < 4; qq++) s += part[b * 4 + qq];
        for (int w = 16*q + 15; w >= 16*q; w--) {
            unsigned word = HB[b * 65 + w];
            unsigned hi = word >> 16, lo = word & 0xffffu;
            int bk = 2 * w + 1;
            s += hi;
            if (bk < GRIDW)     HBsT[bk * 256 + b]       = (unsigned short)s;
            s += lo;
            if (bk - 1 < GRIDW) HBsT[(bk - 1) * 256 + b] = (unsigned short)s;
        }
    }
    __syncthreads();

    // --- phase 3: 32 warps x 3 columns ---
    for (int j = wid; j < GRIDW; j += 32) {
        uint4 w4 = ((const uint4*)(HBsT + j * 256))[lane];    // 8 bins per lane
        unsigned s8 = (w4.x & 0xffffu) + (w4.x >> 16) + (w4.y & 0xffffu) + (w4.y >> 16)
                    + (w4.z & 0xffffu) + (w4.z >> 16) + (w4.w & 0xffffu) + (w4.w >> 16);
        unsigned cum = s8;
        #pragma unroll
        for (int o = 1; o < 32; o <<= 1) {
            unsigned u = __shfl_up_sync(0xffffffffu, cum, o);
            if (lane >= o) cum += u;
        }
        unsigned c = __shfl_sync(0xffffffffu, cum, 31);
        if (c == 0) { if (lane == 0) out[row * GRIDW + j] = 0.0f; continue; }

        unsigned rlo = (c - 1) >> 1, rhi = c >> 1;
        int binlo, binhi; unsigned rl2, rh2;
        find_bin(w4, cum, s8, rlo, lane, binlo, rl2);
        find_bin(w4, cum, s8, rhi, lane, binhi, rh2);

        unsigned klo, khi;
        if (binlo == binhi) {
            int L = (int)min(len[binlo], (unsigned)CAP);
            bin_select2(lists + binlo * CAP, L, j, rl2, rh2, lane, klo, khi);
        } else {
            unsigned t0;
            int L0 = (int)min(len[binlo], (unsigned)CAP);
            bin_select2(lists + binlo * CAP, L0, j, rl2, rl2, lane, klo, t0);
            int L1 = (int)min(len[binhi], (unsigned)CAP);
            bin_select2(lists + binhi * CAP, L1, j, rh2, rh2, lane, khi, t0);
        }

        if (lane == 0) {
            float vlo = ((float)(klo & 0xFFFFFF80u) + 64.0f) * (1.0f / KSCALE) - 48.0f;
            float vhi = ((float)(khi & 0xFFFFFF80u) + 64.0f) * (1.0f / KSCALE) - 48.0f;
            out[row * GRIDW + j] = (0.5f * (vlo + vhi) + 48.0f) * (1.0f / 96.0f);
        }
    }
}

// ---------------- launch ----------------
extern "C" void kernel_launch(void* const* d_in, const int* in_sizes, int n_in,
                              void* d_out, int out_size) {
    const float* pts = (const float*)d_in[0];
    float* out = (float*)d_out;

    cudaFuncSetAttribute(select_kernel, cudaFuncAttributeMaxDynamicSharedMemorySize, SMEM_SEL);

    build_kernel<<<64, 128>>>(pts);
    nn_kernel<<<257, 1024>>>(pts);
    select_kernel<<<GRIDW, 1024, SMEM_SEL>>>(out);
}